// round 7
// baseline (speedup 1.0000x reference)
#include <cuda_runtime.h>

// SPD identity-pad (p=1), input-space mapping:
//   x  : [BC=128][256][2304] fp32   (B*C flattened, row = W*9 = 2304 floats)
//   out: [BC=128][258][2322] fp32
// Kernel 1 (border): write eye(3) to all border cells (1,184,256 elems).
// Kernel 2 (copy)  : iterate over INPUT space -> aligned float4 LDG.128,
//                    8-way bc-group ILP, scalar STG to shifted out position.
//                    No predicates: every input element maps to interior out.

namespace {
constexpr int H         = 256;
constexpr int HO        = 258;
constexpr int ROW_IN    = 256 * 9;              // 2304 floats
constexpr int ROW_IN4   = ROW_IN / 4;           // 576 float4
constexpr int ROW_OUT   = 258 * 9;              // 2322 floats
constexpr int GROUPS    = 8;
constexpr int BC_G      = 128 / GROUPS;         // 16
constexpr int N_IN4_G   = BC_G * H * ROW_IN4;   // 2,359,296 float4 per group
constexpr int STRIDE_I4 = N_IN4_G;              // float4 group stride (input)
constexpr int STRIDE_O  = BC_G * HO * ROW_OUT;  // 9,585,216 float group stride (output)

// border cells per bc-plane: 2 full rows (2*2322) + 256 rows * 18 = 9252
constexpr int BPP  = 2 * ROW_OUT + H * 18;      // 9252
constexpr int N_B  = 128 * BPP;                 // 1,184,256
}

__global__ void __launch_bounds__(256)
spd_border_kernel(float* __restrict__ out)
{
    int idx = blockIdx.x * 256 + threadIdx.x;
    if (idx >= N_B) return;
    int bc = idx / BPP;
    int r  = idx - bc * BPP;
    int i, t;
    if (r < 2 * ROW_OUT) {                       // top/bottom full rows
        i = (r < ROW_OUT) ? 0 : (HO - 1);
        t = (r < ROW_OUT) ? r : (r - ROW_OUT);
    } else {                                     // left/right strips, 18/row
        int r2 = r - 2 * ROW_OUT;
        int rr = r2 / 18;
        int s  = r2 - rr * 18;
        i = rr + 1;
        t = (s < 9) ? s : (ROW_IN + s);          // 0..8  or  2313..2321
    }
    int t9 = t % 9;                              // eye(3): {0,4,8} -> 1
    out[(bc * HO + i) * ROW_OUT + t] = ((t9 & 3) == 0 && t9 != 0) || t9 == 0
                                           ? ((t9 % 4) == 0 ? 1.0f : 0.0f)
                                           : 0.0f;
}

__global__ void __launch_bounds__(256)
spd_copy_kernel(const float4* __restrict__ x4, float* __restrict__ out)
{
    int q = blockIdx.x * 256 + threadIdx.x;      // float4 index, < N_IN4_G
    // q -> (row, c4); row -> (bcl, i_in)
    int row = q / ROW_IN4;                       // 0..4095
    int c4  = q - row * ROW_IN4;                 // 0..575
    int bcl = row >> 8;                          // 0..15
    int i   = row & 255;                         // 0..255

    // output base: interior cell (i+1, col offset 9 + 4*c4)
    int ob = (bcl * HO + i + 1) * ROW_OUT + 9 + c4 * 4;

    float4 v[GROUPS];
#pragma unroll
    for (int k = 0; k < GROUPS; k++)
        v[k] = __ldg(x4 + q + k * STRIDE_I4);    // aligned LDG.128
#pragma unroll
    for (int k = 0; k < GROUPS; k++) {
        float* p = out + ob + k * STRIDE_O;      // odd float offset -> scalar STG
        p[0] = v[k].x; p[1] = v[k].y; p[2] = v[k].z; p[3] = v[k].w;
    }
}

extern "C" void kernel_launch(void* const* d_in, const int* in_sizes, int n_in,
                              void* d_out, int out_size)
{
    const float4* x4 = (const float4*)d_in[0];
    float* out = (float*)d_out;

    int bblocks = (N_B + 255) / 256;             // 4626
    spd_border_kernel<<<bblocks, 256>>>(out);

    int cblocks = N_IN4_G / 256;                 // 9216 exactly
    spd_copy_kernel<<<cblocks, 256>>>(x4, out);
}

// round 9
// speedup vs baseline: 1.2941x; 1.2941x over previous
#include <cuda_runtime.h>

// SPD identity-pad (p=1), register-shift copy:
//   x  : [BC=128][256][2304] fp32 rows (16B-aligned rows: 9216 B each)
//   out: [BC=128][258][2322] fp32
// One block (288 thr) per input row. Loads aligned LDG.128, shifts the odd
// 1-or-3-float output offset via warp shuffle, stores aligned STG.128.
// Borders (eye(3)) folded into the same kernel.

namespace {
constexpr int H       = 256;
constexpr int HO      = 258;
constexpr int ROW_IN  = 2304;   // floats per input row
constexpr int ROW_IN4 = 576;    // float4 per input row
constexpr int ROW_OUT = 2322;   // floats per output row
constexpr int NT      = 288;    // threads per block (9 warps)
}

__global__ void __launch_bounds__(NT)
spd_shift_kernel(const float4* __restrict__ x4, const float* __restrict__ xf,
                 float* __restrict__ out)
{
    const int blk  = blockIdx.x;          // = bc*256 + i  (row id)
    const int bc   = blk >> 8;
    const int i    = blk & 255;
    const int t    = threadIdx.x;         // 0..287
    const int lane = t & 31;

    const int rb4 = blk * ROW_IN4;        // input row base (float4)
    const int rbf = blk * ROW_IN;         // input row base (float)
    // output interior base (float index); b is always odd
    const int b   = (bc * HO + i + 1) * ROW_OUT + 9;
    const int al  = (4 - (b & 3)) & 3;    // 1 or 3 (uniform per block)
    const int a04 = (b + al) >> 2;        // first aligned out float4 index

    const int c0 = t;                     // slot-1 float4 index in row
    const int c1 = t + NT;                // slot-2 float4 index (<= 575)

    float4 v0 = __ldg(x4 + rb4 + c0);
    float4 v1 = __ldg(x4 + rb4 + c1);

    // neighbor (c+1) leading floats via shuffle; lane 31 patches from gmem
    float n0x = __shfl_down_sync(0xffffffffu, v0.x, 1);
    float n0y = __shfl_down_sync(0xffffffffu, v0.y, 1);
    float n0z = __shfl_down_sync(0xffffffffu, v0.z, 1);
    float n1x = __shfl_down_sync(0xffffffffu, v1.x, 1);
    float n1y = __shfl_down_sync(0xffffffffu, v1.y, 1);
    float n1z = __shfl_down_sync(0xffffffffu, v1.z, 1);
    if (lane == 31) {
        const float* p0 = xf + rbf + 4 * (c0 + 1);
        n0x = __ldg(p0 + 0); n0y = __ldg(p0 + 1); n0z = __ldg(p0 + 2);
        if (c1 < ROW_IN4 - 1) {           // c1==575 writes no float4
            const float* p1 = xf + rbf + 4 * (c1 + 1);
            n1x = __ldg(p1 + 0); n1y = __ldg(p1 + 1); n1z = __ldg(p1 + 2);
        }
    }

    float4* out4 = reinterpret_cast<float4*>(out);
    if (al == 1) {
        out4[a04 + c0] = make_float4(v0.y, v0.z, v0.w, n0x);
        if (c1 < ROW_IN4 - 1)
            out4[a04 + c1] = make_float4(v1.y, v1.z, v1.w, n1x);
    } else {  // al == 3
        out4[a04 + c0] = make_float4(v0.w, n0x, n0y, n0z);
        if (c1 < ROW_IN4 - 1)
            out4[a04 + c1] = make_float4(v1.w, n1x, n1y, n1z);
    }

    // head: out[b .. b+al-1] = in[0 .. al-1]
    if (t == 0) {
        out[b] = v0.x;
        if (al == 3) { out[b + 1] = v0.y; out[b + 2] = v0.z; }
    }
    // tail: out[b+al+2300 .. b+2303] = in[al+2300 .. 2303]  (v1 = in4[575])
    if (t == NT - 1) {
        out[b + 2303] = v1.w;
        if (al == 1) { out[b + 2301] = v1.y; out[b + 2302] = v1.z; }
    }

    // left/right border of this out row: 9 + 9 floats of eye(3) pattern
    if (t < 18) {
        int s9  = (t < 9) ? t : (t - 9);
        int pos = (t < 9) ? (b - 9 + t) : (b + ROW_IN + t - 9);
        out[pos] = ((s9 & 3) == 0 && (s9 % 4) == 0) ? 1.0f : 0.0f;
    }

    // full top/bottom border rows, painted by the i==0 / i==255 blocks
    if (i == 0) {
        const int base0 = (bc * HO) * ROW_OUT;
        for (int tt = t; tt < ROW_OUT; tt += NT) {
            int t9 = tt % 9;
            out[base0 + tt] = ((t9 % 4) == 0) ? 1.0f : 0.0f;
        }
    }
    if (i == H - 1) {
        const int baseB = (bc * HO + HO - 1) * ROW_OUT;
        for (int tt = t; tt < ROW_OUT; tt += NT) {
            int t9 = tt % 9;
            out[baseB + tt] = ((t9 % 4) == 0) ? 1.0f : 0.0f;
        }
    }
}

extern "C" void kernel_launch(void* const* d_in, const int* in_sizes, int n_in,
                              void* d_out, int out_size)
{
    const float4* x4 = (const float4*)d_in[0];
    const float*  xf = (const float*)d_in[0];
    float* out = (float*)d_out;
    spd_shift_kernel<<<128 * 256, NT>>>(x4, xf, out);   // 32768 blocks
}